// round 16
// baseline (speedup 1.0000x reference)
#include <cuda_runtime.h>
#include <cuda_bf16.h>

// Problem dims
#define B_  32
#define S_  512
#define I_  256
#define H_  512
#define E_  1024
#define G_  2048
#define NH_ 16
#define HD_ 64
#define T_  16      // tail positions 496..511
#define S0_ 496

// ---------------- scratch (static device globals; no allocation) ----------------
__device__ float g_xg[(size_t)2 * S_ * G_ * B_];   // [dir][s][g][b]
__device__ float g_h [(size_t)2 * S_ * B_ * H_];   // [dir][s][b][j]
__device__ float g_hL[(size_t)B_ * T_ * E_];       // [b][t][e], t = s-496
__device__ float g_K [(size_t)B_ * T_ * E_];       // [m][hk*64+d], m=b*16+t
__device__ float g_V [(size_t)B_ * T_ * E_];
__device__ float g_Q15[(size_t)B_ * T_ * HD_];     // [m][d] head-15 query
__device__ float g_last[B_ * E_];                  // last[b][e]
__device__ float g_we[E_];                         // Wo^T @ Wfc^T
__device__ unsigned g_cnt[2];
__device__ unsigned g_gen[2];

// ---------------- accurate fp32 exp (explicit FMA; fast-math-proof) -------------
__device__ __forceinline__ float expf_acc(float x) {
    x = fminf(fmaxf(x, -87.0f), 87.0f);
    float n = rintf(x * 1.44269504088896341f);
    float r = fmaf(n, -0.693359375f, x);
    r = fmaf(n, 2.12194440e-4f, r);
    float p =             1.9875691500e-4f;
    p = fmaf(p, r, 1.3981999507e-3f);
    p = fmaf(p, r, 8.3334519073e-3f);
    p = fmaf(p, r, 4.1665795894e-2f);
    p = fmaf(p, r, 1.6666665459e-1f);
    p = fmaf(p, r, 5.0000001201e-1f);
    p = fmaf(p * r, r, r) + 1.0f;
    float sc = __int_as_float(((int)n + 127) << 23);
    return p * sc;
}
__device__ __forceinline__ float sigf(float x)   { return 1.0f / (1.0f + expf_acc(-x)); }
__device__ __forceinline__ float tanhf_(float x) { return 1.0f - 2.0f / (expf_acc(2.0f * x) + 1.0f); }

// packed f32x2 FMA: d = a*b + d (elementwise on 2 packed floats)
__device__ __forceinline__ void ffma2(unsigned long long& d,
                                      unsigned long long a, unsigned long long b) {
    asm("fma.rn.f32x2 %0, %1, %2, %0;" : "+l"(d) : "l"(a), "l"(b));
}
__device__ __forceinline__ float pairsum(unsigned long long v0, unsigned long long v1) {
    float a, b, c, d;
    asm("mov.b64 {%0,%1}, %2;" : "=f"(a), "=f"(b) : "l"(v0));
    asm("mov.b64 {%0,%1}, %2;" : "=f"(c), "=f"(d) : "l"(v1));
    return (a + b) + (c + d);
}

// ---------------- K0: reset barrier state (first node of every replay) ----------
__global__ void k_reset() {
    if (threadIdx.x < 2) { g_cnt[threadIdx.x] = 0u; g_gen[threadIdx.x] = 0u; }
}

// ---------------- w_eff[e] = sum_f Wfc[f] * Wo[f][e] ----------------------------
__global__ __launch_bounds__(128) void k_weff(const float* __restrict__ Wo,
                                              const float* __restrict__ Wfc) {
    int e = blockIdx.x * 128 + threadIdx.x;
    float acc = 0.f;
    for (int f = 0; f < E_; ++f) acc += Wfc[f] * Wo[(size_t)f * E_ + e];
    g_we[e] = acc;
}

// ---------------- xg GEMM: C[g][(s,b)] = W[g,:].x[b,s,:] + bias[g] --------------
// M = 2048 gates, N = s_count*32 (n = s_local*32 + b), K = 256.
// 64x64 tiles, 256 threads, 4x4 per thread. Stores coalesced float4 into
// g_xg[dir][s][g][b].
__global__ __launch_bounds__(256) void k_xg2(
    const float* __restrict__ x, const float* __restrict__ W,
    const float* __restrict__ bias, int dir, int s_base)
{
    const int m0 = blockIdx.x * 64;   // gate tile
    const int n0 = blockIdx.y * 64;   // (s,b) tile: 2 s x 32 b
    const int tid = threadIdx.x;
    const int tx = tid & 15;          // n quad
    const int ty = tid >> 4;          // m quad

    __shared__ float As[32 * 68];     // [k][m(g)]
    __shared__ float Bs[32 * 68];     // [k][n(s,b)]

    float acc[4][4];
#pragma unroll
    for (int i = 0; i < 4; ++i)
#pragma unroll
        for (int j = 0; j < 4; ++j) acc[i][j] = 0.f;

    for (int k0 = 0; k0 < I_; k0 += 32) {
        for (int i4 = tid; i4 < 512; i4 += 256) {
            int mm = i4 >> 3, k4 = (i4 & 7) * 4;
            float4 v = *(const float4*)&W[(size_t)(m0 + mm) * I_ + k0 + k4];
            As[(k4 + 0) * 68 + mm] = v.x; As[(k4 + 1) * 68 + mm] = v.y;
            As[(k4 + 2) * 68 + mm] = v.z; As[(k4 + 3) * 68 + mm] = v.w;
        }
        for (int i4 = tid; i4 < 512; i4 += 256) {
            int nn = i4 >> 3, k4 = (i4 & 7) * 4;
            int n = n0 + nn;
            int b = n & 31, s = s_base + (n >> 5);
            float4 v = *(const float4*)&x[(((size_t)b << 9) + s) * I_ + k0 + k4];
            Bs[(k4 + 0) * 68 + nn] = v.x; Bs[(k4 + 1) * 68 + nn] = v.y;
            Bs[(k4 + 2) * 68 + nn] = v.z; Bs[(k4 + 3) * 68 + nn] = v.w;
        }
        __syncthreads();
#pragma unroll 8
        for (int k = 0; k < 32; ++k) {
            float a0 = As[k * 68 + ty * 4 + 0];
            float a1 = As[k * 68 + ty * 4 + 1];
            float a2 = As[k * 68 + ty * 4 + 2];
            float a3 = As[k * 68 + ty * 4 + 3];
            float b0 = Bs[k * 68 + tx * 4 + 0];
            float b1 = Bs[k * 68 + tx * 4 + 1];
            float b2 = Bs[k * 68 + tx * 4 + 2];
            float b3 = Bs[k * 68 + tx * 4 + 3];
            acc[0][0] = fmaf(a0, b0, acc[0][0]); acc[0][1] = fmaf(a0, b1, acc[0][1]);
            acc[0][2] = fmaf(a0, b2, acc[0][2]); acc[0][3] = fmaf(a0, b3, acc[0][3]);
            acc[1][0] = fmaf(a1, b0, acc[1][0]); acc[1][1] = fmaf(a1, b1, acc[1][1]);
            acc[1][2] = fmaf(a1, b2, acc[1][2]); acc[1][3] = fmaf(a1, b3, acc[1][3]);
            acc[2][0] = fmaf(a2, b0, acc[2][0]); acc[2][1] = fmaf(a2, b1, acc[2][1]);
            acc[2][2] = fmaf(a2, b2, acc[2][2]); acc[2][3] = fmaf(a2, b3, acc[2][3]);
            acc[3][0] = fmaf(a3, b0, acc[3][0]); acc[3][1] = fmaf(a3, b1, acc[3][1]);
            acc[3][2] = fmaf(a3, b2, acc[3][2]); acc[3][3] = fmaf(a3, b3, acc[3][3]);
        }
        __syncthreads();
    }
    // store: 4 n's per thread are same s, consecutive b (tx*4 aligned) -> float4
    const int nbase = n0 + tx * 4;
    const int b0 = nbase & 31;
    const int s = s_base + (nbase >> 5);
#pragma unroll
    for (int i = 0; i < 4; ++i) {
        int g = m0 + ty * 4 + i;
        float bi = bias[g];
        float4 v = make_float4(acc[i][0] + bi, acc[i][1] + bi,
                               acc[i][2] + bi, acc[i][3] + bi);
        *(float4*)&g_xg[(((size_t)dir * S_ + s) * G_ + g) * B_ + b0] = v;
    }
}

// ---------------- persistent BiLSTM scan (both directions, one launch) ----------
// 128 CTAs: dir = blockIdx.x>>6 (fwd runs 512 steps, bwd 16). Each CTA owns
// 8 hidden units x 32 batches. Warp lane map: lane = jl2*8 + bq (4 j x 8 b per
// warp) to minimize smem traffic. Packed f32x2 FMAs halve the FFMA issue count.
__global__ __launch_bounds__(256, 1) void k_scan(
    const float* __restrict__ Whf, const float* __restrict__ Whb)
{
    extern __shared__ float smem[];
    float4* Wf4 = (float4*)smem;            // [32 rows][129 f4] (rows padded 516 fl)
    float4* h4  = (float4*)(smem + 32 * 516); // [128 k4][33 f4 (b padded)]

    const int dir = blockIdx.x >> 6;
    const int cta = blockIdx.x & 63;
    const int j0  = cta * 8;
    const int tid = threadIdx.x;
    const int w   = tid >> 5;
    const int lane = tid & 31;
    const int jl  = ((w & 1) << 2) + (lane >> 3);   // 0..7 local j
    const int b   = ((w >> 1) << 3) + (lane & 7);   // 0..31 batch
    const int jg  = j0 + jl;
    const int nsteps = dir ? T_ : S_;

    const float* __restrict__ Whh = dir ? Whb : Whf;

    // Load W_hh slice: rows = 4 gates x 8 local j, 512 k each, padded to 516.
    for (int idx = tid; idx < 4096; idx += 256) {
        int r = idx >> 7, c4 = idx & 127;           // row, float4-col
        int gate = r >> 3, jj = r & 7;
        Wf4[r * 129 + c4] =
            *(const float4*)&Whh[((size_t)(gate * 512 + j0 + jj)) * H_ + c4 * 4];
    }
    __syncthreads();

    const float4* Wi4 = &Wf4[(0 * 8 + jl) * 129];
    const float4* Wff4 = &Wf4[(1 * 8 + jl) * 129];
    const float4* Wg4 = &Wf4[(2 * 8 + jl) * 129];
    const float4* Wo4 = &Wf4[(3 * 8 + jl) * 129];

    float c = 0.f;

    for (int si = 0; si < nsteps; ++si) {
        const int s = dir ? (S_ - 1 - si) : si;
        const size_t xb = ((size_t)dir * S_ + s) * (size_t)G_ * B_;
        float gi = g_xg[xb + (size_t)(0 * 512 + jg) * B_ + b];
        float gf = g_xg[xb + (size_t)(1 * 512 + jg) * B_ + b];
        float gg = g_xg[xb + (size_t)(2 * 512 + jg) * B_ + b];
        float go = g_xg[xb + (size_t)(3 * 512 + jg) * B_ + b];

        if (si > 0) {
            unsigned long long ai0 = 0, ai1 = 0, af0 = 0, af1 = 0;
            unsigned long long ag0 = 0, ag1 = 0, ao0 = 0, ao1 = 0;
#pragma unroll 4
            for (int k4 = 0; k4 < 128; ++k4) {
                ulonglong2 hh = *(const ulonglong2*)&h4[k4 * 33 + b];
                ulonglong2 wi = *(const ulonglong2*)&Wi4[k4];
                ulonglong2 wf = *(const ulonglong2*)&Wff4[k4];
                ulonglong2 wg = *(const ulonglong2*)&Wg4[k4];
                ulonglong2 wo = *(const ulonglong2*)&Wo4[k4];
                ffma2(ai0, wi.x, hh.x); ffma2(ai1, wi.y, hh.y);
                ffma2(af0, wf.x, hh.x); ffma2(af1, wf.y, hh.y);
                ffma2(ag0, wg.x, hh.x); ffma2(ag1, wg.y, hh.y);
                ffma2(ao0, wo.x, hh.x); ffma2(ao1, wo.y, hh.y);
            }
            gi += pairsum(ai0, ai1);
            gf += pairsum(af0, af1);
            gg += pairsum(ag0, ag1);
            go += pairsum(ao0, ao1);
        }
        c = sigf(gf) * c + sigf(gi) * tanhf_(gg);
        float h = sigf(go) * tanhf_(c);

        // store h into [dir][s][b][j]
        const size_t hbase = ((size_t)dir * S_ + s) * (size_t)B_ * H_;
        g_h[hbase + (size_t)b * H_ + jg] = h;

        if (si < nsteps - 1) {
            __threadfence();
            __syncthreads();
            if (tid == 0) {
                unsigned arrived = atomicAdd(&g_cnt[dir], 1u) + 1u;
                if (arrived == 64u) {
                    atomicExch(&g_cnt[dir], 0u);
                    __threadfence();
                    atomicAdd(&g_gen[dir], 1u);
                } else {
                    const unsigned target = (unsigned)(si + 1);
                    while (atomicAdd(&g_gen[dir], 0u) < target) __nanosleep(32);
                }
            }
            __syncthreads();
            // reload full h layer into packed [k4][b] layout (coalesced 128B groups)
            const float* hrow = &g_h[hbase];
            const int rb = tid >> 3;        // batch this thread loads for
            const int ro = tid & 7;         // k4 offset within octet
#pragma unroll
            for (int r = 0; r < 16; ++r) {
                int k4 = ro + 8 * r;
                float4 v = *(const float4*)&hrow[(size_t)rb * H_ + k4 * 4];
                h4[k4 * 33 + rb] = v;
            }
            __syncthreads();
        }
    }
}

// ---------------- gather tail h into hL[b][t][e], e = dir*512 + j ---------------
__global__ __launch_bounds__(128) void k_gather() {
    const int b   = blockIdx.x;
    const int tt  = blockIdx.y;
    const int dir = blockIdx.z;
    const int s   = S0_ + tt;
    const float4* src = (const float4*)&g_h[(((size_t)dir * S_ + s) * B_ + b) * H_];
    float4* dst = (float4*)&g_hL[((size_t)b * T_ + tt) * E_ + dir * H_];
    dst[threadIdx.x] = src[threadIdx.x];
}

// ---------------- K/V projections at tail: out[m][n] = hL[m,:].W[n,:] + bias ----
__global__ __launch_bounds__(256) void k_kv(
    const float* __restrict__ Wk, const float* __restrict__ bk,
    const float* __restrict__ Wv, const float* __restrict__ bv)
{
    const float* __restrict__ W    = blockIdx.z ? Wv : Wk;
    const float* __restrict__ bias = blockIdx.z ? bv : bk;
    float* __restrict__ out        = blockIdx.z ? g_V : g_K;

    const int n0 = blockIdx.x * 64;
    const int m0 = blockIdx.y * 64;
    const int tid = threadIdx.x;
    const int tx = tid & 15;
    const int ty = tid >> 4;

    __shared__ float As[32 * 68];
    __shared__ float Bs[32 * 68];

    float acc[4][4];
#pragma unroll
    for (int i = 0; i < 4; ++i)
#pragma unroll
        for (int j = 0; j < 4; ++j) acc[i][j] = 0.f;

    for (int k0 = 0; k0 < E_; k0 += 32) {
        for (int i4 = tid; i4 < 512; i4 += 256) {
            int m = i4 >> 3, k4 = (i4 & 7) * 4;
            float4 v = *(const float4*)&g_hL[(size_t)(m0 + m) * E_ + k0 + k4];
            As[(k4 + 0) * 68 + m] = v.x; As[(k4 + 1) * 68 + m] = v.y;
            As[(k4 + 2) * 68 + m] = v.z; As[(k4 + 3) * 68 + m] = v.w;
        }
        for (int i4 = tid; i4 < 512; i4 += 256) {
            int n = i4 >> 3, k4 = (i4 & 7) * 4;
            float4 v = *(const float4*)&W[(size_t)(n0 + n) * E_ + k0 + k4];
            Bs[(k4 + 0) * 68 + n] = v.x; Bs[(k4 + 1) * 68 + n] = v.y;
            Bs[(k4 + 2) * 68 + n] = v.z; Bs[(k4 + 3) * 68 + n] = v.w;
        }
        __syncthreads();
#pragma unroll 8
        for (int k = 0; k < 32; ++k) {
            float a0 = As[k * 68 + ty * 4 + 0];
            float a1 = As[k * 68 + ty * 4 + 1];
            float a2 = As[k * 68 + ty * 4 + 2];
            float a3 = As[k * 68 + ty * 4 + 3];
            float b0 = Bs[k * 68 + tx * 4 + 0];
            float b1 = Bs[k * 68 + tx * 4 + 1];
            float b2 = Bs[k * 68 + tx * 4 + 2];
            float b3 = Bs[k * 68 + tx * 4 + 3];
            acc[0][0] = fmaf(a0, b0, acc[0][0]); acc[0][1] = fmaf(a0, b1, acc[0][1]);
            acc[0][2] = fmaf(a0, b2, acc[0][2]); acc[0][3] = fmaf(a0, b3, acc[0][3]);
            acc[1][0] = fmaf(a1, b0, acc[1][0]); acc[1][1] = fmaf(a1, b1, acc[1][1]);
            acc[1][2] = fmaf(a1, b2, acc[1][2]); acc[1][3] = fmaf(a1, b3, acc[1][3]);
            acc[2][0] = fmaf(a2, b0, acc[2][0]); acc[2][1] = fmaf(a2, b1, acc[2][1]);
            acc[2][2] = fmaf(a2, b2, acc[2][2]); acc[2][3] = fmaf(a2, b3, acc[2][3]);
            acc[3][0] = fmaf(a3, b0, acc[3][0]); acc[3][1] = fmaf(a3, b1, acc[3][1]);
            acc[3][2] = fmaf(a3, b2, acc[3][2]); acc[3][3] = fmaf(a3, b3, acc[3][3]);
        }
        __syncthreads();
    }
#pragma unroll
    for (int i = 0; i < 4; ++i) {
        int m = m0 + ty * 4 + i;
#pragma unroll
        for (int j = 0; j < 4; ++j) {
            int n = n0 + tx * 4 + j;
            out[(size_t)m * E_ + n] = acc[i][j] + bias[n];
        }
    }
}

// ---------------- head-15 query at tail: Q15[m][d] ------------------------------
__global__ __launch_bounds__(256) void k_q15(const float* __restrict__ Wq,
                                             const float* __restrict__ bq) {
    const int m = blockIdx.x;
    const int tid = threadIdx.x;
    const int w = tid >> 5, lane = tid & 31;
    __shared__ float hs[E_];
    hs[tid] = g_hL[(size_t)m * E_ + tid];
    hs[tid + 256] = g_hL[(size_t)m * E_ + tid + 256];
    hs[tid + 512] = g_hL[(size_t)m * E_ + tid + 512];
    hs[tid + 768] = g_hL[(size_t)m * E_ + tid + 768];
    __syncthreads();
#pragma unroll
    for (int i = 0; i < 8; ++i) {
        int d = w * 8 + i;
        int f = 15 * HD_ + d;
        const float* wrow = &Wq[(size_t)f * E_];
        float acc = 0.f;
        for (int e = lane; e < E_; e += 32) acc = fmaf(hs[e], wrow[e], acc);
#pragma unroll
        for (int o = 16; o > 0; o >>= 1) acc += __shfl_down_sync(0xffffffffu, acc, o);
        if (lane == 0) g_Q15[m * HD_ + d] = acc + bq[f];
    }
}

// ---------------- per-position head attention + scatter into last ---------------
__global__ __launch_bounds__(128) void k_attn16() {
    const int m = blockIdx.x;
    const int tid = threadIdx.x;
    const int w = tid >> 5, lane = tid & 31;
    __shared__ float q[HD_];
    __shared__ float sc[NH_];
    __shared__ float a[NH_];
    if (tid < HD_) q[tid] = g_Q15[m * HD_ + tid];
    __syncthreads();
#pragma unroll
    for (int i = 0; i < 4; ++i) {
        int hk = w * 4 + i;
        const float* krow = &g_K[(size_t)m * E_ + hk * HD_];
        float acc = fmaf(q[lane], krow[lane], q[lane + 32] * krow[lane + 32]);
#pragma unroll
        for (int o = 16; o > 0; o >>= 1) acc += __shfl_down_sync(0xffffffffu, acc, o);
        if (lane == 0) sc[hk] = acc * 0.125f;
    }
    __syncthreads();
    if (tid == 0) {
        float mx = sc[0];
#pragma unroll
        for (int i = 1; i < NH_; ++i) mx = fmaxf(mx, sc[i]);
        float sum = 0.f;
#pragma unroll
        for (int i = 0; i < NH_; ++i) { float e = expf_acc(sc[i] - mx); a[i] = e; sum += e; }
        float inv = 1.f / sum;
#pragma unroll
        for (int i = 0; i < NH_; ++i) a[i] *= inv;
    }
    __syncthreads();
    if (tid < HD_) {
        const int d = tid;
        float acc = 0.f;
#pragma unroll
        for (int hk = 0; hk < NH_; ++hk)
            acc = fmaf(a[hk], g_V[(size_t)m * E_ + hk * HD_ + d], acc);
        const int b = m >> 4, t = m & 15;
        g_last[b * E_ + t * HD_ + d] = acc;
    }
}

// ---------------- out[b] = sigmoid(last . w_eff + bo.Wfc + bfc) -----------------
__global__ __launch_bounds__(256) void k_final(
    const float* __restrict__ bo, const float* __restrict__ Wfc,
    const float* __restrict__ bfc, float* __restrict__ out)
{
    const int b = blockIdx.x, tid = threadIdx.x;
    float acc = 0.f;
    for (int f = tid; f < E_; f += 256)
        acc += g_last[b * E_ + f] * g_we[f] + bo[f] * Wfc[f];
    __shared__ float red[8];
#pragma unroll
    for (int o = 16; o > 0; o >>= 1) acc += __shfl_xor_sync(0xffffffffu, acc, o);
    if ((tid & 31) == 0) red[tid >> 5] = acc;
    __syncthreads();
    if (tid == 0) {
        float t = 0.f;
#pragma unroll
        for (int i = 0; i < 8; ++i) t += red[i];
        t += bfc[0];
        out[b] = 1.f / (1.f + expf_acc(-t));
    }
}

// ---------------- launch ---------------------------------------------------------
extern "C" void kernel_launch(void* const* d_in, const int* in_sizes, int n_in,
                              void* d_out, int out_size) {
    (void)in_sizes; (void)n_in; (void)out_size;
    const float* x    = (const float*)d_in[0];
    const float* Wihf = (const float*)d_in[1];
    const float* Whhf = (const float*)d_in[2];
    const float* bf   = (const float*)d_in[3];
    const float* Wihb = (const float*)d_in[4];
    const float* Whhb = (const float*)d_in[5];
    const float* bb   = (const float*)d_in[6];
    const float* Wq   = (const float*)d_in[7];
    const float* bq   = (const float*)d_in[8];
    const float* Wk   = (const float*)d_in[9];
    const float* bk   = (const float*)d_in[10];
    const float* Wv   = (const float*)d_in[11];
    const float* bv   = (const float*)d_in[12];
    const float* Wo   = (const float*)d_in[13];
    const float* bo   = (const float*)d_in[14];
    const float* Wfc  = (const float*)d_in[15];
    const float* bfc  = (const float*)d_in[16];
    float* out = (float*)d_out;

    // smem for scan: W 32*516 + h4 128*33*4 floats = 133632 bytes
    cudaFuncSetAttribute(k_scan, cudaFuncAttributeMaxDynamicSharedMemorySize, 133632);

    k_reset  <<<1, 32>>>();
    k_weff   <<<8, 128>>>(Wo, Wfc);
    k_xg2    <<<dim3(32, 256), 256>>>(x, Wihf, bf, 0, 0);    // fwd: all s
    k_xg2    <<<dim3(32, 8),   256>>>(x, Wihb, bb, 1, S0_);  // bwd: tail only
    k_scan   <<<128, 256, 133632>>>(Whhf, Whhb);             // fwd 512 + bwd 16 steps
    k_gather <<<dim3(32, 16, 2), 128>>>();
    k_kv     <<<dim3(16, 8, 2), 256>>>(Wk, bk, Wv, bv);
    k_q15    <<<512, 256>>>(Wq, bq);
    k_attn16 <<<512, 128>>>();
    k_final  <<<32, 256>>>(bo, Wfc, bfc, out);
}